// round 12
// baseline (speedup 1.0000x reference)
#include <cuda_runtime.h>
#include <cstdint>

// RandomTimeMask: out[n,c,l] = x[n,c,l] if ((l - starts[n,c]) mod L) >= L/4 else 0
// x [128,12,32768] fp32, starts [128,12] int32. L=32768, mask_len=8192.
//
// R12: perfectly uniform decomposition. JTOT = 2016 = 7 splits x 288 threads:
// every thread does EXACTLY one paired iteration (1 zero-store + 3 copy vecs,
// all 128B-aligned streams, .cs hints). No loops, no clamping, no duplicate
// writes, no split imbalance. 4 leftover segments (2 partial-mask + 2 kept)
// handled by 4 warps of split 0 via per-lane select.

static constexpr int L    = 32768;
static constexpr int ML   = 8192;          // mask_len
static constexpr int LM1  = L - 1;
static constexpr int VPR  = L / 4;         // 8192 float4 per row
static constexpr int VM1  = VPR - 1;       // 8191
static constexpr int THREADS = 288;        // 9 warps
static constexpr int SPLITS  = 7;          // 7 * 288 = 2016 = JTOT

__global__ __launch_bounds__(THREADS)
void random_time_mask_kernel(const float4* __restrict__ x,
                             const int* __restrict__ starts,
                             float4* __restrict__ out)
{
    const int row   = blockIdx.x / SPLITS;        // 0..1535
    const int split = blockIdx.x - row * SPLITS;  // 0..6
    const int s     = __ldg(&starts[row]);        // 0 <= s < L

    const float4* __restrict__ xr = x   + (size_t)row * VPR;
    float4*       __restrict__ yr = out + (size_t)row * VPR;

    const int sa = s >> 7;                        // segment (128 elems) holding mask start
    const int za = (sa + 1)  << 5;                // zero-stream base (vec units, aligned)
    const int ca = (sa + 65) << 5;                // copy-stream base (vec units, aligned)

    // Exactly one paired iteration per thread.
    const int j = split * THREADS + threadIdx.x;  // 0..2015

    const int mz = (za + j)        & VM1;
    const int c0 = (ca + j)        & VM1;
    const int c1 = (ca + 2016 + j) & VM1;
    const int c2 = (ca + 4032 + j) & VM1;

    const float4 v0 = __ldcs(&xr[c0]);
    const float4 v1 = __ldcs(&xr[c1]);
    const float4 v2 = __ldcs(&xr[c2]);

    const float4 z = make_float4(0.f, 0.f, 0.f, 0.f);
    __stcs(&yr[mz], z);
    __stcs(&yr[c0], v0);
    __stcs(&yr[c1], v1);
    __stcs(&yr[c2], v2);

    // Leftover segments (4 per row): sa and sa+64 (partially masked),
    // sa+254 and sa+255 (fully kept). Per-lane select path, one warp each.
    if (split == 0 && threadIdx.x < 128) {
        const int w    = threadIdx.x >> 5;        // 0..3
        const int lane = threadIdx.x & 31;
        const int seg  = (w == 0) ? sa
                       : (w == 1) ? sa + 64
                       : (w == 2) ? sa + 254
                                  : sa + 255;
        const int v = ((seg << 5) + lane) & VM1;
        float4 t = xr[v];
        const int base = v << 2;
        const int o0 = (base     - s) & LM1;
        const int o1 = (base + 1 - s) & LM1;
        const int o2 = (base + 2 - s) & LM1;
        const int o3 = (base + 3 - s) & LM1;
        t.x = (o0 < ML) ? 0.0f : t.x;
        t.y = (o1 < ML) ? 0.0f : t.y;
        t.z = (o2 < ML) ? 0.0f : t.z;
        t.w = (o3 < ML) ? 0.0f : t.w;
        yr[v] = t;
    }
}

extern "C" void kernel_launch(void* const* d_in, const int* in_sizes, int n_in,
                              void* d_out, int out_size)
{
    const float4* x      = (const float4*)d_in[0];
    const int*    starts = (const int*)d_in[1];
    float4*       out    = (float4*)d_out;

    const int n_rows = in_sizes[1];                // 128*12 = 1536
    random_time_mask_kernel<<<n_rows * SPLITS, THREADS>>>(x, starts, out);
}